// round 6
// baseline (speedup 1.0000x reference)
#include <cuda_runtime.h>
#include <stdint.h>

// Problem constants (fixed by the dataset)
#define NN 5000000          // nodes
#define NGRAPHS 100000
#define NODES_PER_GRAPH 50

// Scratch (allocation-free rule: __device__ globals)
__device__ float g_deg[NN];   // degree, then dis = rsqrt(deg) in-place
__device__ float g_s[NN];     // s[i] = x[i]*w*dis[i]
__device__ float g_agg[NN];   // accumulator, init to s[i] (self loop)

__global__ void k_init_deg(int n) {
    int i = blockIdx.x * blockDim.x + threadIdx.x;
    if (i < n) g_deg[i] = 1.0f;   // self-loop contributes 1 to in-degree
}

// Degree histogram: deg[col[e]] += 1. Reads only the col half of edge_index.
// 4 edges per thread via int4.
__global__ void k_degree(const int* __restrict__ col, int nquads, int E) {
    int i = blockIdx.x * blockDim.x + threadIdx.x;
    const int4* __restrict__ c4 = (const int4*)col;
    if (i < nquads) {
        int4 v = c4[i];
        atomicAdd(&g_deg[v.x], 1.0f);
        atomicAdd(&g_deg[v.y], 1.0f);
        atomicAdd(&g_deg[v.z], 1.0f);
        atomicAdd(&g_deg[v.w], 1.0f);
    }
    // tail (E % 4 edges), handled by thread 0
    if (i == 0) {
        for (int e = nquads * 4; e < E; e++)
            atomicAdd(&g_deg[col[e]], 1.0f);
    }
}

// Per-node: dis = rsqrt(deg); s = x*w*dis; agg starts at s (self-loop term).
__global__ void k_node(const float* __restrict__ x,
                       const float* __restrict__ conv_w, int n) {
    int i = blockIdx.x * blockDim.x + threadIdx.x;
    if (i < n) {
        float w   = __ldg(conv_w);
        float dis = rsqrtf(g_deg[i]);           // deg >= 1 always (self loop)
        float s   = x[i] * w * dis;
        g_deg[i]  = dis;                         // store dis in-place
        g_s[i]    = s;
        g_agg[i]  = s;
    }
}

// Scatter: agg[col[e]] += s[row[e]]. One random L2 read + one REDG per edge.
// 4 edges per thread via int4.
__global__ void k_scatter(const int* __restrict__ row,
                          const int* __restrict__ col,
                          int nquads, int E) {
    int i = blockIdx.x * blockDim.x + threadIdx.x;
    const int4* __restrict__ r4 = (const int4*)row;
    const int4* __restrict__ c4 = (const int4*)col;
    if (i < nquads) {
        int4 r = r4[i];
        int4 c = c4[i];
        float s0 = g_s[r.x];
        float s1 = g_s[r.y];
        float s2 = g_s[r.z];
        float s3 = g_s[r.w];
        atomicAdd(&g_agg[c.x], s0);
        atomicAdd(&g_agg[c.y], s1);
        atomicAdd(&g_agg[c.z], s2);
        atomicAdd(&g_agg[c.w], s3);
    }
    if (i == 0) {
        for (int e = nquads * 4; e < E; e++)
            atomicAdd(&g_agg[col[e]], g_s[row[e]]);
    }
}

// Epilogue: h[i] = agg[i]*dis[i] + conv_b; logits[g,k] = sum_j h[g,j]*fc_w[k,j] + fc_b[k]
__global__ void k_head(const float* __restrict__ conv_b,
                       const float* __restrict__ fc_w,
                       const float* __restrict__ fc_b,
                       float* __restrict__ out, int ngraphs) {
    __shared__ float w0[NODES_PER_GRAPH];
    __shared__ float w1[NODES_PER_GRAPH];
    if (threadIdx.x < NODES_PER_GRAPH) {
        w0[threadIdx.x] = fc_w[threadIdx.x];
        w1[threadIdx.x] = fc_w[NODES_PER_GRAPH + threadIdx.x];
    }
    __syncthreads();
    int g = blockIdx.x * blockDim.x + threadIdx.x;
    if (g < ngraphs) {
        float b  = __ldg(conv_b);
        float a0 = __ldg(&fc_b[0]);
        float a1 = __ldg(&fc_b[1]);
        int base = g * NODES_PER_GRAPH;
        #pragma unroll
        for (int j = 0; j < NODES_PER_GRAPH; j++) {
            float h = fmaf(g_agg[base + j], g_deg[base + j], b);
            a0 = fmaf(h, w0[j], a0);
            a1 = fmaf(h, w1[j], a1);
        }
        out[2 * g]     = a0;
        out[2 * g + 1] = a1;
    }
}

extern "C" void kernel_launch(void* const* d_in, const int* in_sizes, int n_in,
                              void* d_out, int out_size) {
    const float* x      = (const float*)d_in[0];
    const int*   eidx   = (const int*)d_in[1];     // int32! (JAX x64 disabled)
    const float* conv_w = (const float*)d_in[2];
    const float* conv_b = (const float*)d_in[3];
    const float* fc_w   = (const float*)d_in[4];
    const float* fc_b   = (const float*)d_in[5];
    float*       out    = (float*)d_out;

    const int n  = in_sizes[0];           // 5,000,000
    const int E  = in_sizes[1] / 2;       // 80,000,000
    const int nq = E / 4;                 // int4 quads
    const int* row = eidx;
    const int* col = eidx + E;

    const int T = 256;
    int nodeBlocks = (n + T - 1) / T;
    int quadBlocks = (nq + T - 1) / T;
    int headBlocks = (NGRAPHS + T - 1) / T;

    k_init_deg<<<nodeBlocks, T>>>(n);
    k_degree <<<quadBlocks, T>>>(col, nq, E);
    k_node   <<<nodeBlocks, T>>>(x, conv_w, n);
    k_scatter<<<quadBlocks, T>>>(row, col, nq, E);
    k_head   <<<headBlocks, T>>>(conv_b, fc_w, fc_b, out, NGRAPHS);
}